// round 17
// baseline (speedup 1.0000x reference)
#include <cuda_runtime.h>
#include <math.h>
#include <stdint.h>

#define HWPX 16384        // 128*128
#define EPSF 1e-5f

__device__ __forceinline__ float siluf(float v) { return v / (1.0f + __expf(-v)); }

// 256-bit cold read with L2 evict-last hint (channels re-read from L2 later)
__device__ __forceinline__ void ldg_el8(const float* p, float* v) {
    unsigned long long a, b, c, d;
    asm volatile("ld.global.nc.L2::evict_last.v4.b64 {%0,%1,%2,%3}, [%4];"
                 : "=l"(a), "=l"(b), "=l"(c), "=l"(d) : "l"(p));
    v[0] = __uint_as_float((unsigned)a); v[1] = __uint_as_float((unsigned)(a >> 32));
    v[2] = __uint_as_float((unsigned)b); v[3] = __uint_as_float((unsigned)(b >> 32));
    v[4] = __uint_as_float((unsigned)c); v[5] = __uint_as_float((unsigned)(c >> 32));
    v[6] = __uint_as_float((unsigned)d); v[7] = __uint_as_float((unsigned)(d >> 32));
}
// plain 256-bit read (L2-warm path)
__device__ __forceinline__ void ldg8(const float* p, float* v) {
    unsigned long long a, b, c, d;
    asm volatile("ld.global.nc.v4.b64 {%0,%1,%2,%3}, [%4];"
                 : "=l"(a), "=l"(b), "=l"(c), "=l"(d) : "l"(p));
    v[0] = __uint_as_float((unsigned)a); v[1] = __uint_as_float((unsigned)(a >> 32));
    v[2] = __uint_as_float((unsigned)b); v[3] = __uint_as_float((unsigned)(b >> 32));
    v[4] = __uint_as_float((unsigned)c); v[5] = __uint_as_float((unsigned)(c >> 32));
    v[6] = __uint_as_float((unsigned)d); v[7] = __uint_as_float((unsigned)(d >> 32));
}
// evict-first cold read for smem-cached data (no L2 residency wanted)
__device__ __forceinline__ void ldg8_cs(const float* p, float* v) {
    const float4 u0 = __ldcs((const float4*)p);
    const float4 u1 = __ldcs((const float4*)p + 1);
    v[0] = u0.x; v[1] = u0.y; v[2] = u0.z; v[3] = u0.w;
    v[4] = u1.x; v[5] = u1.y; v[6] = u1.z; v[7] = u1.w;
}

// One block per bg-group (128 blocks, 512 threads). R16 + extended smem cache:
// channels 14,15 fully cached + channel 13 rows 0-63 cached (evict-first loads),
// shrinking x's L2 footprint to ~108 MB so all remaining re-reads stay L2-hot.
__global__ __launch_bounds__(512, 1)
void mega(const float* __restrict__ x,
          const float* __restrict__ w1, const float* __restrict__ b1,
          const float* __restrict__ w3, const float* __restrict__ b3,
          const float* __restrict__ gnw, const float* __restrict__ gnb,
          float* __restrict__ out)
{
    extern __shared__ float sm[];
    float* s1  = sm;               // [16][256]
    float* s2  = sm + 4096;        // [16][256]
    float* hwb = sm + 8192;        // [16][258]  means+halo; aliased as h^2 tables after kA
    float* sq1 = sm + 8192;        // [16][128]
    float* sq2 = sm + 8192 + 2048; // [16][128]
    float* xcache = sm + 12320;    // ch14 [16384], ch15 [16384], ch13 rows 0-63 [8192]

    __shared__ float w1s[256], w3s[768], b1s[16], b3s[16];
    __shared__ float statv[64], k1s[16], k2s[16], cpart[16], gbsh[16];
    __shared__ float Csm;

    const int bg   = blockIdx.x;
    const int tid  = threadIdx.x;
    const int lane = tid & 31;
    const int wid  = tid >> 5;                   // 0..15 : one warp per channel
    const float* xb = x   + (size_t)bg * 16 * HWPX;
    float*       ob = out + (size_t)bg * 16 * HWPX;

    // ---- stage tiny weights ----
    if (tid < 256) w1s[tid] = __ldg(w1 + tid);
    for (int i2 = tid; i2 < 768; i2 += 512) w3s[i2] = __ldg(w3 + i2 * 3 + 1); // kw=1 column
    if (tid < 16) { b1s[tid] = __ldg(b1 + tid); b3s[tid] = __ldg(b3 + tid); gbsh[tid] = __ldg(gnb + tid); }

    // ================= P1: row + col means (pipelined, ascending, 256-bit) =====
    {
        const int c = wid;
        const float* g = xb + c * HWPX;
        float* hwc = hwb + c * 258;
        float* xcw = (c >= 14) ? (xcache + (c - 14) * HWPX) : (xcache + 2 * HWPX); // ch13 partial
        const int half = lane >> 4;              // 0/1
        const int seg  = lane & 15;
        const int colbase = seg * 8;
        float cs[8];
        #pragma unroll
        for (int j = 0; j < 8; j++) cs[j] = 0.f;
        float va[4][8], vb[4][8];

        #define P1_LOAD(LOADFN, BUF, I0)                                           \
        {                                                                          \
            _Pragma("unroll")                                                      \
            for (int k = 0; k < 4; k++)                                            \
                LOADFN(g + ((I0) + 2 * k + half) * 128 + colbase, BUF[k]);         \
        }
        #define P1_BODY(BUF, I0, DO_CACHE)                                         \
        {                                                                          \
            _Pragma("unroll")                                                      \
            for (int k = 0; k < 4; k++) {                                          \
                const int row = (I0) + 2 * k + half;                               \
                if (DO_CACHE) {                                                    \
                    *(float4*)(xcw + row * 128 + colbase)     = *(float4*)&BUF[k][0]; \
                    *(float4*)(xcw + row * 128 + colbase + 4) = *(float4*)&BUF[k][4]; \
                }                                                                  \
                float r = 0.f;                                                     \
                _Pragma("unroll")                                                  \
                for (int j = 0; j < 8; j++) { cs[j] += BUF[k][j]; r += BUF[k][j]; }\
                r += __shfl_xor_sync(0xffffffffu, r, 1);                           \
                r += __shfl_xor_sync(0xffffffffu, r, 2);                           \
                r += __shfl_xor_sync(0xffffffffu, r, 4);                           \
                r += __shfl_xor_sync(0xffffffffu, r, 8);                           \
                if (seg == 0) hwc[1 + row] = r * (1.f / 128.f);                    \
            }                                                                      \
        }

        if (c < 13) {
            P1_LOAD(ldg_el8, va, 0)
            #pragma unroll 1
            for (int i0 = 0; i0 < 128; i0 += 16) {
                P1_LOAD(ldg_el8, vb, i0 + 8)
                P1_BODY(va, i0, 0)
                if (i0 + 16 < 128) P1_LOAD(ldg_el8, va, i0 + 16)
                P1_BODY(vb, i0 + 8, 0)
            }
        } else if (c == 13) {
            // rows 0-63: evict-first + smem cache; rows 64-127: evict_last (L2)
            P1_LOAD(ldg8_cs, va, 0)
            #pragma unroll 1
            for (int i0 = 0; i0 < 64; i0 += 16) {
                P1_LOAD(ldg8_cs, vb, i0 + 8)
                P1_BODY(va, i0, 1)
                if (i0 + 16 < 64) P1_LOAD(ldg8_cs, va, i0 + 16)
                P1_BODY(vb, i0 + 8, 1)
            }
            P1_LOAD(ldg_el8, va, 64)
            #pragma unroll 1
            for (int i0 = 64; i0 < 128; i0 += 16) {
                P1_LOAD(ldg_el8, vb, i0 + 8)
                P1_BODY(va, i0, 0)
                if (i0 + 16 < 128) P1_LOAD(ldg_el8, va, i0 + 16)
                P1_BODY(vb, i0 + 8, 0)
            }
        } else {
            P1_LOAD(ldg8_cs, va, 0)
            #pragma unroll 1
            for (int i0 = 0; i0 < 128; i0 += 16) {
                P1_LOAD(ldg8_cs, vb, i0 + 8)
                P1_BODY(va, i0, 1)
                if (i0 + 16 < 128) P1_LOAD(ldg8_cs, va, i0 + 16)
                P1_BODY(vb, i0 + 8, 1)
            }
        }
        #undef P1_LOAD
        #undef P1_BODY

        #pragma unroll
        for (int j = 0; j < 8; j++) cs[j] += __shfl_xor_sync(0xffffffffu, cs[j], 16);
        if (half == 0) {
            #pragma unroll
            for (int j = 0; j < 8; j++)
                hwc[129 + colbase + j] = cs[j] * (1.f / 128.f);
        }
        if (lane == 0) { hwc[0] = 0.f; hwc[257] = 0.f; }   // conv halo
    }
    __syncthreads();

    // ================= kA: channel mix over concat length 256 =================
    for (int idx = tid; idx < 4096; idx += 512) {
        const int o = idx >> 8, l = idx & 255;
        float a1 = b1s[o], a2 = b3s[o];
        #pragma unroll
        for (int i = 0; i < 16; i++) {
            const float* h = hwb + i * 258 + l;
            const float h0 = h[0], h1 = h[1], h2 = h[2];
            a1 = fmaf(w1s[o * 16 + i], h1, a1);
            const int wb = (o * 16 + i) * 3;
            a2 = fmaf(w3s[wb], h0, fmaf(w3s[wb + 1], h1, fmaf(w3s[wb + 2], h2, a2)));
        }
        s1[o * 256 + l] = siluf(a1);
        s2[o * 256 + l] = siluf(a2);
    }
    __syncthreads();
    // h^2 tables (into dead hwb region)
    for (int idx = tid; idx < 2048; idx += 512) {
        const int c = idx >> 7, i = idx & 127;
        const float a = s1[c * 256 + i];
        const float b = s2[c * 256 + i];
        sq1[idx] = a * a;
        sq2[idx] = b * b;
    }
    __syncthreads();

    // ================= P2: separable moments (descending; smem path for cached) ========
    {
        const int c = wid;
        const float* g = xb + c * HWPX;
        const int half = lane >> 4;
        const int seg  = lane & 15;
        const int colbase = seg * 8;
        float wa8[8], wb8[8], wa2[8], wb2[8];
        #pragma unroll
        for (int j = 0; j < 8; j++) {
            wa8[j] = s1[c * 256 + 128 + colbase + j];
            wb8[j] = s2[c * 256 + 128 + colbase + j];
            wa2[j] = wa8[j] * wa8[j];
            wb2[j] = wb8[j] * wb8[j];
        }
        float sa = 0.f, qa = 0.f, sb = 0.f, qb = 0.f;

        #define P2_ACC(VPTR, I)                                                    \
        {                                                                          \
            const float h1  = s1[c * 256 + (I)];                                   \
            const float h2  = s2[c * 256 + (I)];                                   \
            const float h1q = sq1[c * 128 + (I)];                                  \
            const float h2q = sq2[c * 128 + (I)];                                  \
            float d1 = 0.f, e1 = 0.f, d2 = 0.f, e2 = 0.f;                          \
            _Pragma("unroll")                                                      \
            for (int j = 0; j < 8; j++) {                                          \
                const float v = (VPTR)[j];                                         \
                const float v2 = v * v;                                            \
                d1 = fmaf(v, wa8[j], d1);                                          \
                e1 = fmaf(v2, wa2[j], e1);                                         \
                d2 = fmaf(v, wb8[j], d2);                                          \
                e2 = fmaf(v2, wb2[j], e2);                                         \
            }                                                                      \
            sa = fmaf(h1, d1, sa);                                                 \
            qa = fmaf(h1q, e1, qa);                                                \
            sb = fmaf(h2, d2, sb);                                                 \
            qb = fmaf(h2q, e2, qb);                                                \
        }
        #define P2_LOAD(BUF, I0)                                                   \
        {                                                                          \
            _Pragma("unroll")                                                      \
            for (int k = 0; k < 4; k++)                                            \
                ldg8(g + ((I0) + 2 * k + half) * 128 + colbase, BUF[k]);           \
        }
        #define P2_BODY(BUF, I0)                                                   \
        {                                                                          \
            _Pragma("unroll")                                                      \
            for (int k = 0; k < 4; k++) { P2_ACC(BUF[k], (I0) + 2 * k + half) }    \
        }
        #define P2_SMEM_RANGE(XCW, I_LO, I_HI)                                     \
        {                                                                          \
            _Pragma("unroll 1")                                                    \
            for (int i0 = (I_LO); i0 < (I_HI); i0 += 8) {                          \
                _Pragma("unroll")                                                  \
                for (int k = 0; k < 4; k++) {                                      \
                    const int i = i0 + 2 * k + half;                               \
                    const float* p = (XCW) + i * 128 + colbase;                    \
                    float vv[8];                                                   \
                    const float4 u0 = *(const float4*)p;                           \
                    const float4 u1 = *(const float4*)(p + 4);                     \
                    vv[0] = u0.x; vv[1] = u0.y; vv[2] = u0.z; vv[3] = u0.w;        \
                    vv[4] = u1.x; vv[5] = u1.y; vv[6] = u1.z; vv[7] = u1.w;        \
                    P2_ACC(vv, i)                                                  \
                }                                                                  \
            }                                                                      \
        }

        if (c < 13) {
            float va[4][8], vb[4][8];
            P2_LOAD(va, 120)
            #pragma unroll 1
            for (int i0 = 120; i0 >= 0; i0 -= 16) {
                P2_LOAD(vb, i0 - 8)
                P2_BODY(va, i0)
                if (i0 - 16 >= 0) P2_LOAD(va, i0 - 16)
                P2_BODY(vb, i0 - 8)
            }
        } else if (c == 13) {
            float va[4][8], vb[4][8];
            P2_LOAD(va, 120)
            #pragma unroll 1
            for (int i0 = 120; i0 >= 64; i0 -= 16) {       // rows 64..127 from L2
                P2_LOAD(vb, i0 - 8)
                P2_BODY(va, i0)
                if (i0 - 16 >= 64) P2_LOAD(va, i0 - 16)
                P2_BODY(vb, i0 - 8)
            }
            P2_SMEM_RANGE(xcache + 2 * HWPX, 0, 64)        // rows 0..63 from smem
        } else {
            P2_SMEM_RANGE(xcache + (c - 14) * HWPX, 0, 128)
        }
        #undef P2_ACC
        #undef P2_LOAD
        #undef P2_BODY
        #undef P2_SMEM_RANGE

        #pragma unroll
        for (int off = 16; off; off >>= 1) {
            sa += __shfl_down_sync(0xffffffffu, sa, off);
            qa += __shfl_down_sync(0xffffffffu, qa, off);
            sb += __shfl_down_sync(0xffffffffu, sb, off);
            qb += __shfl_down_sync(0xffffffffu, qb, off);
        }
        if (lane == 0) { statv[c * 4] = sa; statv[c * 4 + 1] = qa; statv[c * 4 + 2] = sb; statv[c * 4 + 3] = qb; }
    }
    __syncthreads();

    // ================= kB: scalars =================
    if (tid < 16) {
        float m = -1e30f;
        #pragma unroll
        for (int i = 0; i < 16; i++) m = fmaxf(m, gbsh[i]);
        float se = 0.f;
        #pragma unroll
        for (int i = 0; i < 16; i++) se += __expf(gbsh[i] - m);
        const float a = __expf(gbsh[tid] - m) / se;        // a1 == a2 == softmax(gn_b)
        const float S1 = statv[tid * 4], Q1 = statv[tid * 4 + 1];
        const float S2 = statv[tid * 4 + 2], Q2 = statv[tid * 4 + 3];
        const float mu1 = S1 * (1.f / 16384.f);
        const float r1  = rsqrtf(Q1 * (1.f / 16384.f) - mu1 * mu1 + EPSF);
        const float mu2 = S2 * (1.f / 16384.f);
        const float r2  = rsqrtf(Q2 * (1.f / 16384.f) - mu2 * mu2 + EPSF);
        const float gw = __ldg(gnw + tid);
        k1s[tid] = a * gw * r1;
        k2s[tid] = a * gw * r2;
        cpart[tid] = a * (2.f * gbsh[tid] - gw * (mu1 * r1 + mu2 * r2));
    }
    __syncthreads();
    if (tid == 0) {
        float s = 0.f;
        #pragma unroll
        for (int i = 0; i < 16; i++) s += cpart[i];
        Csm = s;
    }
    // fold k1/k2 into the i-side silu tables (j-side stays unscaled)
    for (int idx = tid; idx < 2048; idx += 512) {
        const int c = idx >> 7, i = idx & 127;
        s1[c * 256 + i] *= k1s[c];
        s2[c * 256 + i] *= k2s[c];
    }
    __syncthreads();

    // ================= C: wts + gate + output (ascending; cached data from smem) =========
    {
        const int rloc = tid >> 5;              // 0..15 rows per sub-iteration
        const float Cc = Csm;
        #pragma unroll 1
        for (int s = 0; s < 8; s++) {
            const int i = s * 16 + rloc;
            float4 v[16];
            float4 w4 = make_float4(Cc, Cc, Cc, Cc);
            #pragma unroll
            for (int c = 0; c < 16; c++) {
                if (c < 13)
                    v[c] = __ldcs((const float4*)(xb + c * HWPX + i * 128) + lane);
                else if (c == 13)
                    v[c] = (s < 4)
                         ? *((const float4*)(xcache + 2 * HWPX + i * 128) + lane)
                         : __ldcs((const float4*)(xb + c * HWPX + i * 128) + lane);
                else
                    v[c] = *((const float4*)(xcache + (c - 14) * HWPX + i * 128) + lane);
                const float a1 = s1[c * 256 + i];
                const float a2 = s2[c * 256 + i];
                const float4 j1 = *(const float4*)(s1 + c * 256 + 128 + 4 * lane);
                const float4 j2 = *(const float4*)(s2 + c * 256 + 128 + 4 * lane);
                w4.x += v[c].x * fmaf(a1, j1.x, a2 * j2.x);
                w4.y += v[c].y * fmaf(a1, j1.y, a2 * j2.y);
                w4.z += v[c].z * fmaf(a1, j1.z, a2 * j2.z);
                w4.w += v[c].w * fmaf(a1, j1.w, a2 * j2.w);
            }
            float4 sw;
            sw.x = siluf(w4.x); sw.y = siluf(w4.y); sw.z = siluf(w4.z); sw.w = siluf(w4.w);
            #pragma unroll
            for (int c = 0; c < 16; c++) {
                float4 o4;
                o4.x = v[c].x * sw.x; o4.y = v[c].y * sw.y;
                o4.z = v[c].z * sw.z; o4.w = v[c].w * sw.w;
                __stcs((float4*)(ob + c * HWPX + i * 128) + lane, o4);
            }
        }
    }
}

// ---------------- launch ----------------
extern "C" void kernel_launch(void* const* d_in, const int* in_sizes, int n_in,
                              void* d_out, int out_size) {
    const float* x    = (const float*)d_in[0];
    const float* w1   = (const float*)d_in[1];
    const float* b1   = (const float*)d_in[2];
    const float* w3   = (const float*)d_in[3];
    const float* b3   = (const float*)d_in[4];
    const float* gn_w = (const float*)d_in[5];
    const float* gn_b = (const float*)d_in[6];
    float* out = (float*)d_out;

    // s1 4096 + s2 4096 + hwb 4128 + xcache (2*16384 + 8192) = 53280 floats = 213120 B
    const int smem_bytes = 53280 * (int)sizeof(float);
    static bool attr_done = false;
    if (!attr_done) {
        cudaFuncSetAttribute(mega, cudaFuncAttributeMaxDynamicSharedMemorySize, smem_bytes);
        attr_done = true;
    }
    mega<<<128, 512, smem_bytes>>>(x, w1, b1, w3, b3, gn_w, gn_b, out);
}